// round 3
// baseline (speedup 1.0000x reference)
#include <cuda_runtime.h>
#include <math.h>

// ---------------------------------------------------------------------------
// Compile-time stiffness coefficients (exact cofactor inverse of the 6x6
// compliance matrix, which is block-diagonal: asymmetric 3x3 block + 0.075*I).
// ---------------------------------------------------------------------------
constexpr double K_a = 1.0 / 0.21;          // 1/Ep
constexpr double K_b = 0.4 / 0.21;          // vp/Ep
constexpr double K_c = 0.4;                 // vp  (the asymmetry in row 2)
constexpr double K_A11 = K_a * K_a - K_b * K_c;
constexpr double K_DET = K_a * K_A11
                       - K_b * (K_b * (K_a + K_c))
                       - K_b * (K_c * (K_a + K_b));
constexpr float CM0  = (float)(K_A11 / K_DET);                      // diag(0,0)=(1,1)
constexpr float CM1  = (float)((K_b * (K_a + K_c)) / K_DET);        // (0,1)=(1,0)
constexpr float CM23 = (float)(((K_b + K_c) * (K_a + K_b)) / K_DET);// (0,2)+(2,0)
constexpr float CM4  = (float)((K_a * K_a - K_b * K_b) / K_DET);    // (2,2)
constexpr float CSH  = (float)((0.21 / 2.8) * 0.25);                // 0.075 * 0.5^2

// Reduction state (zero at module load; the finalizing block restores zeros
// every call, so the kernel stays deterministic across graph replays).
__device__ double       g_sum  = 0.0;
__device__ unsigned int g_cnt  = 0u;
__device__ unsigned int g_done = 0u;

__device__ __forceinline__ void accum_point(
    float ux, float uy, float uz,
    float vx, float vy, float vz,
    float wx, float wy, float wz,
    float sdf, float& acc, int& cnt)
{
    float e0 = ux, e1 = vy, e2 = wz;
    float s3 = uy + vx;
    float s4 = uz + wx;
    float s5 = wy + vz;
    float q = CM0 * (e0 * e0 + e1 * e1)
            + 2.0f * CM1 * (e0 * e1)
            + CM23 * ((e0 + e1) * e2)
            + CM4 * (e2 * e2)
            + CSH * (s3 * s3 + s4 * s4 + s5 * s5);
    if (sdf < 1e-8f) {
        acc += q * q;
        cnt += 1;
    }
}

__global__ void __launch_bounds__(256)
biomech_loss_kernel(const float4* __restrict__ U,
                    const float4* __restrict__ V,
                    const float4* __restrict__ W,
                    const float4* __restrict__ S,
                    const float*  __restrict__ gu,
                    const float*  __restrict__ gv,
                    const float*  __restrict__ gw,
                    const float*  __restrict__ sd,
                    float* __restrict__ out,
                    int ngroups, int n)
{
    int t = blockIdx.x * blockDim.x + threadIdx.x;
    float acc = 0.0f;
    int   cnt = 0;

    if (t < ngroups) {
        // 4 points per thread: 12 floats per gradient array = 3x float4 each,
        // plus one float4 of sdf. All loads issued up front (MLP = 10).
        float4 s  = S[t];
        float4 u0 = U[3 * t + 0], u1 = U[3 * t + 1], u2 = U[3 * t + 2];
        float4 v0 = V[3 * t + 0], v1 = V[3 * t + 1], v2 = V[3 * t + 2];
        float4 w0 = W[3 * t + 0], w1 = W[3 * t + 1], w2 = W[3 * t + 2];

        accum_point(u0.x, u0.y, u0.z, v0.x, v0.y, v0.z, w0.x, w0.y, w0.z, s.x, acc, cnt);
        accum_point(u0.w, u1.x, u1.y, v0.w, v1.x, v1.y, w0.w, w1.x, w1.y, s.y, acc, cnt);
        accum_point(u1.z, u1.w, u2.x, v1.z, v1.w, v2.x, w1.z, w1.w, w2.x, s.z, acc, cnt);
        accum_point(u2.y, u2.z, u2.w, v2.y, v2.z, v2.w, w2.y, w2.z, w2.w, s.w, acc, cnt);
    }

    // Scalar tail (N % 4 != 0) handled by global thread 0. N=4M -> no-op.
    if (t == 0) {
        for (int p = 4 * ngroups; p < n; p++) {
            accum_point(gu[3 * p], gu[3 * p + 1], gu[3 * p + 2],
                        gv[3 * p], gv[3 * p + 1], gv[3 * p + 2],
                        gw[3 * p], gw[3 * p + 1], gw[3 * p + 2],
                        sd[p], acc, cnt);
        }
    }

    // Warp reduction.
    #pragma unroll
    for (int o = 16; o > 0; o >>= 1) {
        acc += __shfl_down_sync(0xFFFFFFFFu, acc, o);
        cnt += __shfl_down_sync(0xFFFFFFFFu, cnt, o);
    }

    __shared__ float sacc[8];
    __shared__ int   scnt[8];
    int wid  = threadIdx.x >> 5;
    int lane = threadIdx.x & 31;
    if (lane == 0) { sacc[wid] = acc; scnt[wid] = cnt; }
    __syncthreads();

    if (wid == 0) {
        acc = (lane < 8) ? sacc[lane] : 0.0f;
        cnt = (lane < 8) ? scnt[lane] : 0;
        #pragma unroll
        for (int o = 4; o > 0; o >>= 1) {
            acc += __shfl_down_sync(0xFFFFFFFFu, acc, o);
            cnt += __shfl_down_sync(0xFFFFFFFFu, cnt, o);
        }
        if (lane == 0) {
            atomicAdd(&g_sum, (double)acc);
            atomicAdd(&g_cnt, (unsigned int)cnt);
            __threadfence();
            unsigned int ticket = atomicAdd(&g_done, 1u);
            if (ticket == gridDim.x - 1u) {
                // Last block: all prior atomics are visible (fence + atomic order).
                double       total = atomicAdd(&g_sum, 0.0);
                unsigned int c     = atomicAdd(&g_cnt, 0u);
                out[0] = (float)(sqrt(total) / (double)c);
                // Restore zero-state for the next (graph-replayed) call.
                g_sum  = 0.0;
                g_cnt  = 0u;
                g_done = 0u;
            }
        }
    }
}

extern "C" void kernel_launch(void* const* d_in, const int* in_sizes, int n_in,
                              void* d_out, int out_size)
{
    const float* gu = (const float*)d_in[0];
    const float* gv = (const float*)d_in[1];
    const float* gw = (const float*)d_in[2];
    const float* sd = (const float*)d_in[3];
    float* out = (float*)d_out;

    int n  = in_sizes[3];      // number of points (gt_sdf element count)
    int ng = n / 4;            // float4 groups
    int blocks = (ng + 255) / 256;
    if (blocks < 1) blocks = 1;

    biomech_loss_kernel<<<blocks, 256>>>(
        (const float4*)gu, (const float4*)gv, (const float4*)gw, (const float4*)sd,
        gu, gv, gw, sd, out, ng, n);
}

// round 5
// speedup vs baseline: 1.1393x; 1.1393x over previous
#include <cuda_runtime.h>
#include <math.h>

// ---------------------------------------------------------------------------
// Compile-time stiffness coefficients (exact cofactor inverse of the 6x6
// compliance matrix, which is block-diagonal: asymmetric 3x3 block + 0.075*I).
// ---------------------------------------------------------------------------
constexpr double K_a = 1.0 / 0.21;          // 1/Ep
constexpr double K_b = 0.4 / 0.21;          // vp/Ep
constexpr double K_c = 0.4;                 // vp  (the asymmetry in row 2)
constexpr double K_A11 = K_a * K_a - K_b * K_c;
constexpr double K_DET = K_a * K_A11
                       - K_b * (K_b * (K_a + K_c))
                       - K_b * (K_c * (K_a + K_b));
constexpr float CM0  = (float)(K_A11 / K_DET);                      // diag(0,0)=(1,1)
constexpr float CM1  = (float)((K_b * (K_a + K_c)) / K_DET);        // (0,1)=(1,0)
constexpr float CM23 = (float)(((K_b + K_c) * (K_a + K_b)) / K_DET);// (0,2)+(2,0)
constexpr float CM4  = (float)((K_a * K_a - K_b * K_b) / K_DET);    // (2,2)
constexpr float CSH  = (float)((0.21 / 2.8) * 0.25);                // 0.075 * 0.5^2

// Reduction state (zero at module load; the finalizing block restores zeros
// every call, so the kernel stays deterministic across graph replays).
__device__ double       g_sum  = 0.0;
__device__ unsigned int g_cnt  = 0u;
__device__ unsigned int g_done = 0u;

__device__ __forceinline__ void accum_point(
    float ux, float uy, float uz,
    float vx, float vy, float vz,
    float wx, float wy, float wz,
    float sdf, float& acc, int& cnt)
{
    float e0 = ux, e1 = vy, e2 = wz;
    float s3 = uy + vx;
    float s4 = uz + wx;
    float s5 = wy + vz;
    float q = CM0 * (e0 * e0 + e1 * e1)
            + 2.0f * CM1 * (e0 * e1)
            + CM23 * ((e0 + e1) * e2)
            + CM4 * (e2 * e2)
            + CSH * (s3 * s3 + s4 * s4 + s5 * s5);
    if (sdf < 1e-8f) {
        acc += q * q;
        cnt += 1;
    }
}

__global__ void __launch_bounds__(256)
biomech_loss_kernel(const float4* __restrict__ U,
                    const float4* __restrict__ V,
                    const float4* __restrict__ W,
                    const float4* __restrict__ S,
                    const float*  __restrict__ gu,
                    const float*  __restrict__ gv,
                    const float*  __restrict__ gw,
                    const float*  __restrict__ sd,
                    float* __restrict__ out,
                    int ngroups, int n)
{
    const int stride = gridDim.x * blockDim.x;
    float acc = 0.0f;
    int   cnt = 0;

    // Persistent grid-stride loop: one wave of CTAs, each thread walks
    // multiple float4-groups. Loads of the next iteration overlap the
    // reduction math of the current one.
    for (int t = blockIdx.x * blockDim.x + threadIdx.x; t < ngroups; t += stride) {
        // 4 points per thread-iteration: 3x float4 per gradient array + 1
        // float4 of sdf, streaming loads (evict-first; single-pass data).
        float4 s  = __ldcs(&S[t]);
        float4 u0 = __ldcs(&U[3 * t + 0]);
        float4 u1 = __ldcs(&U[3 * t + 1]);
        float4 u2 = __ldcs(&U[3 * t + 2]);
        float4 v0 = __ldcs(&V[3 * t + 0]);
        float4 v1 = __ldcs(&V[3 * t + 1]);
        float4 v2 = __ldcs(&V[3 * t + 2]);
        float4 w0 = __ldcs(&W[3 * t + 0]);
        float4 w1 = __ldcs(&W[3 * t + 1]);
        float4 w2 = __ldcs(&W[3 * t + 2]);

        accum_point(u0.x, u0.y, u0.z, v0.x, v0.y, v0.z, w0.x, w0.y, w0.z, s.x, acc, cnt);
        accum_point(u0.w, u1.x, u1.y, v0.w, v1.x, v1.y, w0.w, w1.x, w1.y, s.y, acc, cnt);
        accum_point(u1.z, u1.w, u2.x, v1.z, v1.w, v2.x, w1.z, w1.w, w2.x, s.z, acc, cnt);
        accum_point(u2.y, u2.z, u2.w, v2.y, v2.z, v2.w, w2.y, w2.z, w2.w, s.w, acc, cnt);
    }

    // Scalar tail (N % 4 != 0) handled by one thread. N=4M -> no-op.
    if (blockIdx.x == 0 && threadIdx.x == 0) {
        for (int p = 4 * ngroups; p < n; p++) {
            accum_point(gu[3 * p], gu[3 * p + 1], gu[3 * p + 2],
                        gv[3 * p], gv[3 * p + 1], gv[3 * p + 2],
                        gw[3 * p], gw[3 * p + 1], gw[3 * p + 2],
                        sd[p], acc, cnt);
        }
    }

    // Warp reduction.
    #pragma unroll
    for (int o = 16; o > 0; o >>= 1) {
        acc += __shfl_down_sync(0xFFFFFFFFu, acc, o);
        cnt += __shfl_down_sync(0xFFFFFFFFu, cnt, o);
    }

    __shared__ float sacc[8];
    __shared__ int   scnt[8];
    int wid  = threadIdx.x >> 5;
    int lane = threadIdx.x & 31;
    if (lane == 0) { sacc[wid] = acc; scnt[wid] = cnt; }
    __syncthreads();

    if (wid == 0) {
        acc = (lane < 8) ? sacc[lane] : 0.0f;
        cnt = (lane < 8) ? scnt[lane] : 0;
        #pragma unroll
        for (int o = 4; o > 0; o >>= 1) {
            acc += __shfl_down_sync(0xFFFFFFFFu, acc, o);
            cnt += __shfl_down_sync(0xFFFFFFFFu, cnt, o);
        }
        if (lane == 0) {
            atomicAdd(&g_sum, (double)acc);
            atomicAdd(&g_cnt, (unsigned int)cnt);
            __threadfence();
            unsigned int ticket = atomicAdd(&g_done, 1u);
            if (ticket == gridDim.x - 1u) {
                // Last block: all prior atomics are visible (fence + atomic order).
                double       total = atomicAdd(&g_sum, 0.0);
                unsigned int c     = atomicAdd(&g_cnt, 0u);
                out[0] = (float)(sqrt(total) / (double)c);
                // Restore zero-state for the next (graph-replayed) call.
                g_sum  = 0.0;
                g_cnt  = 0u;
                g_done = 0u;
            }
        }
    }
}

extern "C" void kernel_launch(void* const* d_in, const int* in_sizes, int n_in,
                              void* d_out, int out_size)
{
    const float* gu = (const float*)d_in[0];
    const float* gv = (const float*)d_in[1];
    const float* gw = (const float*)d_in[2];
    const float* sd = (const float*)d_in[3];
    float* out = (float*)d_out;

    int n  = in_sizes[3];      // number of points (gt_sdf element count)
    int ng = n / 4;            // float4 groups

    // One full wave: 6 CTAs/SM (reg-limited occupancy at 38 regs, 256 thr).
    // GB300 has 152 SMs; query confirms, fallback stays sane on error.
    int nsm = 152;
    if (cudaDeviceGetAttribute(&nsm, cudaDevAttrMultiProcessorCount, 0)
        != cudaSuccess || nsm <= 0) {
        nsm = 152;
    }
    int blocks = 6 * nsm;
    int max_needed = (ng + 255) / 256;
    if (blocks > max_needed) blocks = max_needed;
    if (blocks < 1) blocks = 1;

    biomech_loss_kernel<<<blocks, 256>>>(
        (const float4*)gu, (const float4*)gv, (const float4*)gw, (const float4*)sd,
        gu, gv, gw, sd, out, ng, n);
}